// round 15
// baseline (speedup 1.0000x reference)
#include <cuda_runtime.h>
#include <cuda_fp16.h>
#include <cstdint>

#define NN    8192
#define FIN   256
#define FOUT  64
#define RT    128
#define NBLK  256      // 64 row-tiles x 4 j-quarters
#define JT    2048     // j per block
#define NSUB  32       // subtiles of 64 j

typedef unsigned int u32;

// ---- global scratch (no cudaMalloc allowed) ----
__device__ float g_s1[NN];
__device__ __align__(16) float g_s2[NN];
__device__ __align__(16) __half g_Wh_hi[NN * FOUT];   // [j][f] row-major
__device__ __align__(16) float g_Dp[NBLK * RT * FOUT];
__device__ float g_Zp[NBLK * RT];

static __device__ __forceinline__ u32 smem_u32(const void* p) {
    u32 a;
    asm("{ .reg .u64 t; cvta.to.shared.u64 t, %1; cvt.u32.u64 %0, t; }" : "=r"(a) : "l"(p));
    return a;
}

#define MMA(d, a, b0_, b1_)                                                     \
    asm volatile("mma.sync.aligned.m16n8k16.row.col.f32.f16.f16.f32 "           \
        "{%0,%1,%2,%3}, {%4,%5,%6,%7}, {%8,%9}, {%0,%1,%2,%3};"                 \
        : "+f"(d[0]), "+f"(d[1]), "+f"(d[2]), "+f"(d[3])                        \
        : "r"(a[0]), "r"(a[1]), "r"(a[2]), "r"(a[3]), "r"(b0_), "r"(b1_))

#define MMAT(d, a0_, a1_, a2_, a3_, b0_, b1_)                                   \
    asm volatile("mma.sync.aligned.m16n8k8.row.col.f32.tf32.tf32.f32 "          \
        "{%0,%1,%2,%3}, {%4,%5,%6,%7}, {%8,%9}, {%0,%1,%2,%3};"                 \
        : "+f"(d[0]), "+f"(d[1]), "+f"(d[2]), "+f"(d[3])                        \
        : "r"(a0_), "r"(a1_), "r"(a2_), "r"(a3_), "r"(b0_), "r"(b1_))

static __device__ __forceinline__ u32 tf32cvt(float f) {
    u32 r;
    asm("cvt.rna.tf32.f32 %0, %1;" : "=r"(r) : "f"(f));
    return r;
}

#define CPA(dst, src) asm volatile("cp.async.cg.shared.global [%0], [%1], 16;" :: "r"(dst), "l"(src) : "memory")
#define CPC() asm volatile("cp.async.commit_group;" ::: "memory")
#define CPW0() asm volatile("cp.async.wait_group 0;" ::: "memory")

// ---------------------------------------------------------------------------
// Kernel 1 (v5): Wh = h@W via 3xTF32 MMA; s1/s2; f16 Wh. (unchanged)
// ---------------------------------------------------------------------------
__global__ __launch_bounds__(256, 2) void k_prep(const float* __restrict__ h,
                                                 const float* __restrict__ W,
                                                 const float* __restrict__ a) {
    extern __shared__ float dsm[];
    float* hS = dsm;                    // [32][260]
    float* Wt = dsm + 32 * 260;         // [64][260]  ([n][k])
    __shared__ float redS[2][4][32];
    int t = threadIdx.x, lane = t & 31, wid = t >> 5;
    int rowBase = blockIdx.x * 32;

    const float4* hb4 = (const float4*)(h + (size_t)rowBase * FIN);
    #pragma unroll
    for (int p = 0; p < 8; p++) {
        int idx4 = t + p * 256;
        int r = idx4 >> 6, c4 = idx4 & 63;
        float4 v = hb4[idx4];
        *(float4*)(hS + r * 260 + c4 * 4) = v;
    }
    {
        int n_ = t & 63, rg = t >> 6;
        #pragma unroll
        for (int u16 = 0; u16 < 16; u16++) {
            int u = rg * 16 + u16;
            float4 v;
            v.x = __ldg(&W[(4 * u + 0) * FOUT + n_]);
            v.y = __ldg(&W[(4 * u + 1) * FOUT + n_]);
            v.z = __ldg(&W[(4 * u + 2) * FOUT + n_]);
            v.w = __ldg(&W[(4 * u + 3) * FOUT + n_]);
            *(float4*)(Wt + n_ * 260 + 4 * u) = v;
        }
    }
    __syncthreads();

    int mt = wid & 1, nq = wid >> 1;
    int g = lane >> 2, tc = lane & 3;
    const float* A0 = hS + (mt * 16 + g) * 260;
    const float* A1 = A0 + 8 * 260;

    float D[2][4];
    #pragma unroll
    for (int nt = 0; nt < 2; nt++) { D[nt][0] = D[nt][1] = D[nt][2] = D[nt][3] = 0.f; }

    #pragma unroll 4
    for (int ks = 0; ks < 32; ks++) {
        int k0 = ks * 8;
        float a00 = A0[k0 + tc],     a10 = A1[k0 + tc];
        float a01 = A0[k0 + tc + 4], a11 = A1[k0 + tc + 4];
        u32 ah0 = tf32cvt(a00), ah1 = tf32cvt(a10), ah2 = tf32cvt(a01), ah3 = tf32cvt(a11);
        u32 al0 = tf32cvt(a00 - __uint_as_float(ah0));
        u32 al1 = tf32cvt(a10 - __uint_as_float(ah1));
        u32 al2 = tf32cvt(a01 - __uint_as_float(ah2));
        u32 al3 = tf32cvt(a11 - __uint_as_float(ah3));
        #pragma unroll
        for (int nt = 0; nt < 2; nt++) {
            const float* B = Wt + (nq * 16 + nt * 8 + g) * 260 + k0;
            float b0f = B[tc], b1f = B[tc + 4];
            u32 bh0 = tf32cvt(b0f), bh1 = tf32cvt(b1f);
            u32 bl0 = tf32cvt(b0f - __uint_as_float(bh0));
            u32 bl1 = tf32cvt(b1f - __uint_as_float(bh1));
            MMAT(D[nt], ah0, ah1, ah2, ah3, bh0, bh1);
            MMAT(D[nt], ah0, ah1, ah2, ah3, bl0, bl1);
            MMAT(D[nt], al0, al1, al2, al3, bh0, bh1);
        }
    }

    int r0 = rowBase + mt * 16 + g;
    float p1r0 = 0.f, p2r0 = 0.f, p1r1 = 0.f, p2r1 = 0.f;
    u32* whH32 = (u32*)g_Wh_hi;
    #pragma unroll
    for (int nt = 0; nt < 2; nt++) {
        int n0 = nq * 16 + nt * 8 + tc * 2;
        float a1a = a[n0], a1b = a[n0 + 1];
        float a2a = a[FOUT + n0], a2b = a[FOUT + n0 + 1];
        p1r0 += D[nt][0] * a1a + D[nt][1] * a1b;
        p2r0 += D[nt][0] * a2a + D[nt][1] * a2b;
        p1r1 += D[nt][2] * a1a + D[nt][3] * a1b;
        p2r1 += D[nt][2] * a2a + D[nt][3] * a2b;
        #pragma unroll
        for (int rr = 0; rr < 2; rr++) {
            int row = r0 + rr * 8;
            __half2 hp = __halves2half2(__float2half(D[nt][rr * 2]),
                                        __float2half(D[nt][rr * 2 + 1]));
            whH32[row * 32 + nq * 8 + nt * 4 + tc] = *(u32*)&hp;
        }
    }
    #pragma unroll
    for (int o = 1; o <= 2; o <<= 1) {
        p1r0 += __shfl_xor_sync(0xffffffffu, p1r0, o);
        p2r0 += __shfl_xor_sync(0xffffffffu, p2r0, o);
        p1r1 += __shfl_xor_sync(0xffffffffu, p1r1, o);
        p2r1 += __shfl_xor_sync(0xffffffffu, p2r1, o);
    }
    if (tc == 0) {
        redS[0][nq][mt * 16 + g]     = p1r0;
        redS[0][nq][mt * 16 + 8 + g] = p1r1;
        redS[1][nq][mt * 16 + g]     = p2r0;
        redS[1][nq][mt * 16 + 8 + g] = p2r1;
    }
    __syncthreads();
    if (t < 32) {
        g_s1[rowBase + t] = (redS[0][0][t] + redS[0][1][t]) + (redS[0][2][t] + redS[0][3][t]);
        g_s2[rowBase + t] = (redS[1][0][t] + redS[1][1][t]) + (redS[1][2][t] + redS[1][3][t]);
    }
}

// ---------------------------------------------------------------------------
// Kernel 2 (v6): single-pass f16 flash-GAT with
//   - packed ex2.approx.f16x2 weights (2 XU/q instead of 3; mask e=-127
//     underflows to exact 0.0 in f16)
//   - Z via ones-column MMA: B-tile row pad bytes 128..143 = n-cols 64..71,
//     col 64 = 1.0 -> D8 accumulates Sum(w). No FADD z, no shfl reduce.
// static smem: s2S 8KB + whH 2x9216 = 26.4KB
// ---------------------------------------------------------------------------
__global__ __launch_bounds__(256, 2) void k_main(const int* __restrict__ adj) {
    __shared__ float s2S[JT];
    __shared__ __align__(16) char whH[2 * 9216];

    int t = threadIdx.x, lane = t & 31, wid = t >> 5;
    int blk = blockIdx.x;
    int i0 = (blk >> 2) * RT;
    int jb = (blk & 3) * JT;
    int g = lane >> 2, tc = lane & 3;

    #pragma unroll
    for (int q = 0; q < JT / 256; q++) s2S[t + q * 256] = g_s2[jb + t + q * 256];

    // ones-tile init: pad bytes 128..143 of each of 64 rows x 2 buffers.
    // u32 pattern {0x00003C00,0,0,0}: col64 = f16 1.0, cols 65..71 = 0.
    if (t < 128) {
        int buf = t >> 6, j = t & 63;
        *(uint4*)(whH + buf * 9216 + j * 144 + 128) = make_uint4(0x00003C00u, 0u, 0u, 0u);
    }

    int row0 = i0 + wid * 16 + g;
    float s1v0 = g_s1[row0], s1v1 = g_s1[row0 + 8];
    const int* aR0 = adj + (size_t)row0 * NN + jb;
    const int* aR1 = aR0 + (size_t)8 * NN;

    float D[8][4], D8[4];
    #pragma unroll
    for (int n = 0; n < 8; n++) { D[n][0] = D[n][1] = D[n][2] = D[n][3] = 0.f; }
    D8[0] = D8[1] = D8[2] = D8[3] = 0.f;

    u32 whHb = smem_u32(whH);
    int laneoff = (((lane >> 3) & 1) * 8 + (lane & 7)) * 144 + (lane >> 4) * 16;
    int oneoff  = (((lane >> 3) & 1) * 8 + (lane & 7)) * 144 + 128;

    int sj0 = t >> 3, sc = t & 7;
    const char* gH = (const char*)g_Wh_hi;

    auto issueTile = [&](int s) {
        int jn = jb + s * 64;
        const char* sH = gH + ((size_t)(jn + sj0) * 8 + sc) * 16;
        u32 dH = whHb + (s & 1) * 9216 + sj0 * 144 + sc * 16;
        CPA(dH, sH);  CPA(dH + 32 * 144, sH + 4096);
    };

    auto loadBits = [&](int s) -> u32 {
        const int* b0 = aR0 + s * 64;
        const int* b1 = aR1 + s * 64;
        u32 m = 0;
        #pragma unroll
        for (int ks = 0; ks < 4; ks++) {
            int2 v0 = *(const int2*)(b0 + ks * 16 + tc * 2);
            int2 v1 = *(const int2*)(b1 + ks * 16 + tc * 2);
            int2 v2 = *(const int2*)(b0 + ks * 16 + tc * 2 + 8);
            int2 v3 = *(const int2*)(b1 + ks * 16 + tc * 2 + 8);
            u32 base = ks * 8;
            m |= (v0.x > 0 ? 1u : 0u) << (base + 0);
            m |= (v0.y > 0 ? 1u : 0u) << (base + 1);
            m |= (v1.x > 0 ? 1u : 0u) << (base + 2);
            m |= (v1.y > 0 ? 1u : 0u) << (base + 3);
            m |= (v2.x > 0 ? 1u : 0u) << (base + 4);
            m |= (v2.y > 0 ? 1u : 0u) << (base + 5);
            m |= (v3.x > 0 ? 1u : 0u) << (base + 6);
            m |= (v3.y > 0 ? 1u : 0u) << (base + 7);
        }
        return m;
    };

    issueTile(0);
    CPC();
    u32 bC = loadBits(0), bN = 0;

    for (int st = 0; st < NSUB; st++) {
        int bo = (st & 1) * 9216;
        CPW0();             // tile st resident
        __syncthreads();    // also orders ones-tile init before first use

        if (st < NSUB - 1) {
            issueTile(st + 1);
            CPC();
            bN = loadBits(st + 1);
        }

        // ---- A-frags: masked e in f32, pack, ex2.approx.f16x2 ----
        u32 AH[16];
        #pragma unroll
        for (int ks = 0; ks < 4; ks++) {
            int j0 = ks * 16;
            float2 sa = *(const float2*)&s2S[st * 64 + j0 + tc * 2];
            float2 sb = *(const float2*)&s2S[st * 64 + j0 + tc * 2 + 8];
            #pragma unroll
            for (int q = 0; q < 4; q++) {
                u32 bb = bC >> (ks * 8 + q * 2);
                float s1v  = (q & 1) ? s1v1 : s1v0;
                float2 s2p = (q >> 1) ? sb : sa;
                float x0 = s1v + s2p.x, x1 = s1v + s2p.y;
                float l0 = fmaxf(x0, 0.2f * x0), l1 = fmaxf(x1, 0.2f * x1);
                float e0 = fmaf(l0, 1.44269504f, -8.0f);   // w = exp(lr)*2^-8
                float e1 = fmaf(l1, 1.44269504f, -8.0f);
                e0 = (bb & 1u) ? e0 : -127.0f;             // 2^-127 -> f16 0
                e1 = (bb & 2u) ? e1 : -127.0f;
                u32 ep, wv;
                asm("cvt.rn.f16x2.f32 %0, %1, %2;" : "=r"(ep) : "f"(e1), "f"(e0));
                asm("ex2.approx.f16x2 %0, %1;" : "=r"(wv) : "r"(ep));
                AH[ks * 4 + q] = wv;
            }
        }

        // ---- MMA loop (single pass + ones-column for Z) ----
        #pragma unroll
        for (int ks = 0; ks < 4; ks++) {
            u32* ahi = AH + ks * 4;
            u32 abH = whHb + bo + ks * 16 * 144 + laneoff;
            #pragma unroll
            for (int nb = 0; nb < 4; nb++) {
                u32 bh0, bh1, bh2, bh3;
                asm volatile("ldmatrix.sync.aligned.m8n8.x4.trans.shared.b16 {%0,%1,%2,%3}, [%4];"
                    : "=r"(bh0), "=r"(bh1), "=r"(bh2), "=r"(bh3) : "r"(abH + nb * 32));
                MMA(D[nb * 2],     ahi, bh0, bh1);
                MMA(D[nb * 2 + 1], ahi, bh2, bh3);
            }
            u32 o0, o1;
            asm volatile("ldmatrix.sync.aligned.m8n8.x2.trans.shared.b16 {%0,%1}, [%2];"
                : "=r"(o0), "=r"(o1) : "r"(whHb + bo + ks * 16 * 144 + oneoff));
            MMA(D8, ahi, o0, o1);
        }
        bC = bN;
    }

    // ---- epilogue: Z from D8 (col 64), partial stores ----
    if (tc == 0) {
        g_Zp[blk * RT + wid * 16 + g]     = D8[0];
        g_Zp[blk * RT + wid * 16 + 8 + g] = D8[2];
    }
    float* db = g_Dp + (size_t)blk * RT * FOUT + (size_t)(wid * 16 + g) * FOUT + tc * 2;
    #pragma unroll
    for (int nt = 0; nt < 8; nt++) {
        *(float2*)(db + nt * 8)             = make_float2(D[nt][0], D[nt][1]);
        *(float2*)(db + 8 * FOUT + nt * 8)  = make_float2(D[nt][2], D[nt][3]);
    }
}

// ---------------------------------------------------------------------------
// Kernel 3: combine 4 j-quarters: out = elu(SumD/SumZ)
// ---------------------------------------------------------------------------
__global__ __launch_bounds__(256) void k_comb(float* __restrict__ out) {
    int idx = blockIdx.x * 256 + threadIdx.x;   // x4 floats
    int i  = idx >> 4;
    int f4 = (idx & 15) * 4;
    int rt = i >> 7, r = i & 127;
    float4 d = make_float4(0.f, 0.f, 0.f, 0.f);
    float z = 0.f;
    #pragma unroll
    for (int p = 0; p < 4; p++) {
        int b = rt * 4 + p;
        const float4 dp = *(const float4*)(g_Dp + (size_t)b * (RT * FOUT) + r * FOUT + f4);
        d.x += dp.x; d.y += dp.y; d.z += dp.z; d.w += dp.w;
        z += g_Zp[b * RT + r];
    }
    float inv = 1.0f / z;
    float v[4] = {d.x * inv, d.y * inv, d.z * inv, d.w * inv};
    #pragma unroll
    for (int c = 0; c < 4; c++) v[c] = (v[c] > 0.f) ? v[c] : expm1f(v[c]);
    *(float4*)(out + (size_t)i * FOUT + f4) = make_float4(v[0], v[1], v[2], v[3]);
}

// ---------------------------------------------------------------------------
extern "C" void kernel_launch(void* const* d_in, const int* in_sizes, int n_in,
                              void* d_out, int out_size) {
    const float* h   = (const float*)d_in[0];
    const int*   adj = (const int*)  d_in[1];
    const float* W   = (const float*)d_in[2];
    const float* a   = (const float*)d_in[3];
    float* out = (float*)d_out;

    cudaFuncSetAttribute(k_prep, cudaFuncAttributeMaxDynamicSharedMemorySize, 99840);
    k_prep<<<NN / 32, 256, 99840>>>(h, W, a);
    k_main<<<NBLK, 256>>>(adj);
    k_comb<<<NN * FOUT / 4 / 256, 256>>>(out);
}

// round 16
// speedup vs baseline: 1.0162x; 1.0162x over previous
#include <cuda_runtime.h>
#include <cuda_fp16.h>
#include <cstdint>

#define NN    8192
#define FIN   256
#define FOUT  64
#define RT    128
#define NBLK  256      // 64 row-tiles x 4 j-quarters
#define JT    2048     // j per block
#define NSUB  16       // subtiles of 128 j
#define TILEB 18432    // 128 rows x 144B

typedef unsigned int u32;

// ---- global scratch (no cudaMalloc allowed) ----
__device__ float g_s1[NN];
__device__ __align__(16) float g_s2[NN];
__device__ __align__(16) __half g_Wh_hi[NN * FOUT];   // [j][f] row-major
__device__ __align__(16) float g_Dp[NBLK * RT * FOUT];
__device__ float g_Zp[NBLK * RT];

static __device__ __forceinline__ u32 smem_u32(const void* p) {
    u32 a;
    asm("{ .reg .u64 t; cvta.to.shared.u64 t, %1; cvt.u32.u64 %0, t; }" : "=r"(a) : "l"(p));
    return a;
}

#define MMA(d, a, b0_, b1_)                                                     \
    asm volatile("mma.sync.aligned.m16n8k16.row.col.f32.f16.f16.f32 "           \
        "{%0,%1,%2,%3}, {%4,%5,%6,%7}, {%8,%9}, {%0,%1,%2,%3};"                 \
        : "+f"(d[0]), "+f"(d[1]), "+f"(d[2]), "+f"(d[3])                        \
        : "r"(a[0]), "r"(a[1]), "r"(a[2]), "r"(a[3]), "r"(b0_), "r"(b1_))

#define MMAT(d, a0_, a1_, a2_, a3_, b0_, b1_)                                   \
    asm volatile("mma.sync.aligned.m16n8k8.row.col.f32.tf32.tf32.f32 "          \
        "{%0,%1,%2,%3}, {%4,%5,%6,%7}, {%8,%9}, {%0,%1,%2,%3};"                 \
        : "+f"(d[0]), "+f"(d[1]), "+f"(d[2]), "+f"(d[3])                        \
        : "r"(a0_), "r"(a1_), "r"(a2_), "r"(a3_), "r"(b0_), "r"(b1_))

static __device__ __forceinline__ u32 tf32cvt(float f) {
    u32 r;
    asm("cvt.rna.tf32.f32 %0, %1;" : "=r"(r) : "f"(f));
    return r;
}

#define CPA(dst, src) asm volatile("cp.async.cg.shared.global [%0], [%1], 16;" :: "r"(dst), "l"(src) : "memory")
#define CPC() asm volatile("cp.async.commit_group;" ::: "memory")
#define CPW0() asm volatile("cp.async.wait_group 0;" ::: "memory")

// ---------------------------------------------------------------------------
// Kernel 1 (v5): Wh = h@W via 3xTF32 MMA; s1/s2; f16 Wh. (unchanged from R14)
// ---------------------------------------------------------------------------
__global__ __launch_bounds__(256, 2) void k_prep(const float* __restrict__ h,
                                                 const float* __restrict__ W,
                                                 const float* __restrict__ a) {
    extern __shared__ float dsm[];
    float* hS = dsm;                    // [32][260]
    float* Wt = dsm + 32 * 260;         // [64][260]  ([n][k])
    __shared__ float redS[2][4][32];
    int t = threadIdx.x, lane = t & 31, wid = t >> 5;
    int rowBase = blockIdx.x * 32;

    const float4* hb4 = (const float4*)(h + (size_t)rowBase * FIN);
    #pragma unroll
    for (int p = 0; p < 8; p++) {
        int idx4 = t + p * 256;
        int r = idx4 >> 6, c4 = idx4 & 63;
        float4 v = hb4[idx4];
        *(float4*)(hS + r * 260 + c4 * 4) = v;
    }
    {
        int n_ = t & 63, rg = t >> 6;
        #pragma unroll
        for (int u16 = 0; u16 < 16; u16++) {
            int u = rg * 16 + u16;
            float4 v;
            v.x = __ldg(&W[(4 * u + 0) * FOUT + n_]);
            v.y = __ldg(&W[(4 * u + 1) * FOUT + n_]);
            v.z = __ldg(&W[(4 * u + 2) * FOUT + n_]);
            v.w = __ldg(&W[(4 * u + 3) * FOUT + n_]);
            *(float4*)(Wt + n_ * 260 + 4 * u) = v;
        }
    }
    __syncthreads();

    int mt = wid & 1, nq = wid >> 1;
    int g = lane >> 2, tc = lane & 3;
    const float* A0 = hS + (mt * 16 + g) * 260;
    const float* A1 = A0 + 8 * 260;

    float D[2][4];
    #pragma unroll
    for (int nt = 0; nt < 2; nt++) { D[nt][0] = D[nt][1] = D[nt][2] = D[nt][3] = 0.f; }

    #pragma unroll 4
    for (int ks = 0; ks < 32; ks++) {
        int k0 = ks * 8;
        float a00 = A0[k0 + tc],     a10 = A1[k0 + tc];
        float a01 = A0[k0 + tc + 4], a11 = A1[k0 + tc + 4];
        u32 ah0 = tf32cvt(a00), ah1 = tf32cvt(a10), ah2 = tf32cvt(a01), ah3 = tf32cvt(a11);
        u32 al0 = tf32cvt(a00 - __uint_as_float(ah0));
        u32 al1 = tf32cvt(a10 - __uint_as_float(ah1));
        u32 al2 = tf32cvt(a01 - __uint_as_float(ah2));
        u32 al3 = tf32cvt(a11 - __uint_as_float(ah3));
        #pragma unroll
        for (int nt = 0; nt < 2; nt++) {
            const float* B = Wt + (nq * 16 + nt * 8 + g) * 260 + k0;
            float b0f = B[tc], b1f = B[tc + 4];
            u32 bh0 = tf32cvt(b0f), bh1 = tf32cvt(b1f);
            u32 bl0 = tf32cvt(b0f - __uint_as_float(bh0));
            u32 bl1 = tf32cvt(b1f - __uint_as_float(bh1));
            MMAT(D[nt], ah0, ah1, ah2, ah3, bh0, bh1);
            MMAT(D[nt], ah0, ah1, ah2, ah3, bl0, bl1);
            MMAT(D[nt], al0, al1, al2, al3, bh0, bh1);
        }
    }

    int r0 = rowBase + mt * 16 + g;
    float p1r0 = 0.f, p2r0 = 0.f, p1r1 = 0.f, p2r1 = 0.f;
    u32* whH32 = (u32*)g_Wh_hi;
    #pragma unroll
    for (int nt = 0; nt < 2; nt++) {
        int n0 = nq * 16 + nt * 8 + tc * 2;
        float a1a = a[n0], a1b = a[n0 + 1];
        float a2a = a[FOUT + n0], a2b = a[FOUT + n0 + 1];
        p1r0 += D[nt][0] * a1a + D[nt][1] * a1b;
        p2r0 += D[nt][0] * a2a + D[nt][1] * a2b;
        p1r1 += D[nt][2] * a1a + D[nt][3] * a1b;
        p2r1 += D[nt][2] * a2a + D[nt][3] * a2b;
        #pragma unroll
        for (int rr = 0; rr < 2; rr++) {
            int row = r0 + rr * 8;
            __half2 hp = __halves2half2(__float2half(D[nt][rr * 2]),
                                        __float2half(D[nt][rr * 2 + 1]));
            whH32[row * 32 + nq * 8 + nt * 4 + tc] = *(u32*)&hp;
        }
    }
    #pragma unroll
    for (int o = 1; o <= 2; o <<= 1) {
        p1r0 += __shfl_xor_sync(0xffffffffu, p1r0, o);
        p2r0 += __shfl_xor_sync(0xffffffffu, p2r0, o);
        p1r1 += __shfl_xor_sync(0xffffffffu, p1r1, o);
        p2r1 += __shfl_xor_sync(0xffffffffu, p2r1, o);
    }
    if (tc == 0) {
        redS[0][nq][mt * 16 + g]     = p1r0;
        redS[0][nq][mt * 16 + 8 + g] = p1r1;
        redS[1][nq][mt * 16 + g]     = p2r0;
        redS[1][nq][mt * 16 + 8 + g] = p2r1;
    }
    __syncthreads();
    if (t < 32) {
        g_s1[rowBase + t] = (redS[0][0][t] + redS[0][1][t]) + (redS[0][2][t] + redS[0][3][t]);
        g_s2[rowBase + t] = (redS[1][0][t] + redS[1][1][t]) + (redS[1][2][t] + redS[1][3][t]);
    }
}

// ---------------------------------------------------------------------------
// Kernel 2 (v7): R14 math (f32 ex2, FADD z) + 128-j subtiles:
// HALF the __syncthreads (16 vs 32), double latency-hiding per stage.
// Adj masks split into two 64-j halves issued at different points to keep
// register pressure at R14 levels and spread LDG bursts.
// static smem: s2S 8KB + whH 2x18432 = 44.9KB (2 blocks/SM)
// ---------------------------------------------------------------------------
__global__ __launch_bounds__(256, 2) void k_main(const int* __restrict__ adj) {
    __shared__ float s2S[JT];
    __shared__ __align__(16) char whH[2 * TILEB];

    int t = threadIdx.x, lane = t & 31, wid = t >> 5;
    int blk = blockIdx.x;
    int i0 = (blk >> 2) * RT;
    int jb = (blk & 3) * JT;
    int g = lane >> 2, tc = lane & 3;

    #pragma unroll
    for (int q = 0; q < JT / 256; q++) s2S[t + q * 256] = g_s2[jb + t + q * 256];

    int row0 = i0 + wid * 16 + g;
    float s1v0 = g_s1[row0], s1v1 = g_s1[row0 + 8];
    const int* aR0 = adj + (size_t)row0 * NN + jb;
    const int* aR1 = aR0 + (size_t)8 * NN;

    float D[8][4];
    #pragma unroll
    for (int n = 0; n < 8; n++) { D[n][0] = D[n][1] = D[n][2] = D[n][3] = 0.f; }
    float z0 = 0.f, z1 = 0.f;

    u32 whHb = smem_u32(whH);
    int laneoff = (((lane >> 3) & 1) * 8 + (lane & 7)) * 144 + (lane >> 4) * 16;

    // staging: thread t -> tile row t>>1, 4 chunks of 16B at (t&1)*64
    int sj0 = t >> 1, sco = (t & 1) * 4;
    const char* gH = (const char*)g_Wh_hi;

    auto issueTile = [&](int s) {
        int jn = jb + s * 128;
        const char* sH = gH + ((size_t)(jn + sj0) * 8 + sco) * 16;
        u32 dH = whHb + (s & 1) * TILEB + sj0 * 144 + sco * 16;
        #pragma unroll
        for (int c = 0; c < 4; c++) CPA(dH + c * 16, sH + c * 16);
    };

    // adj bitmask for 64-j half hf of subtile s: bit(ks*8 + q*2 + {0,1})
    auto loadBits = [&](int s, int hf) -> u32 {
        const int* b0 = aR0 + s * 128 + hf * 64;
        const int* b1 = aR1 + s * 128 + hf * 64;
        u32 m = 0;
        #pragma unroll
        for (int ks = 0; ks < 4; ks++) {
            int2 v0 = *(const int2*)(b0 + ks * 16 + tc * 2);
            int2 v1 = *(const int2*)(b1 + ks * 16 + tc * 2);
            int2 v2 = *(const int2*)(b0 + ks * 16 + tc * 2 + 8);
            int2 v3 = *(const int2*)(b1 + ks * 16 + tc * 2 + 8);
            u32 base = ks * 8;
            m |= (v0.x > 0 ? 1u : 0u) << (base + 0);
            m |= (v0.y > 0 ? 1u : 0u) << (base + 1);
            m |= (v1.x > 0 ? 1u : 0u) << (base + 2);
            m |= (v1.y > 0 ? 1u : 0u) << (base + 3);
            m |= (v2.x > 0 ? 1u : 0u) << (base + 4);
            m |= (v2.y > 0 ? 1u : 0u) << (base + 5);
            m |= (v3.x > 0 ? 1u : 0u) << (base + 6);
            m |= (v3.y > 0 ? 1u : 0u) << (base + 7);
        }
        return m;
    };

    // one 64-j half: A-frags from mask, then 4 k-steps of MMA
    auto half64 = [&](int st, int hf, u32 bm) {
        int bo = (st & 1) * TILEB;
        u32 AH[16];
        #pragma unroll
        for (int ks = 0; ks < 4; ks++) {
            int j0 = st * 128 + hf * 64 + ks * 16;
            float2 sa = *(const float2*)&s2S[j0 + tc * 2];
            float2 sb = *(const float2*)&s2S[j0 + tc * 2 + 8];
            #pragma unroll
            for (int q = 0; q < 4; q++) {
                u32 bb = bm >> (ks * 8 + q * 2);
                float s1v  = (q & 1) ? s1v1 : s1v0;
                float2 s2p = (q >> 1) ? sb : sa;
                float x0 = s1v + s2p.x, x1 = s1v + s2p.y;
                float l0 = fmaxf(x0, 0.2f * x0), l1 = fmaxf(x1, 0.2f * x1);
                float e0 = fmaf(l0, 1.44269504f, -8.0f);   // w = exp(lr)*2^-8
                float e1 = fmaf(l1, 1.44269504f, -8.0f);
                e0 = (bb & 1u) ? e0 : -127.0f;
                e1 = (bb & 2u) ? e1 : -127.0f;
                float w0, w1;
                asm("ex2.approx.ftz.f32 %0, %1;" : "=f"(w0) : "f"(e0));
                asm("ex2.approx.ftz.f32 %0, %1;" : "=f"(w1) : "f"(e1));
                if (q & 1) z1 += w0 + w1; else z0 += w0 + w1;
                asm("cvt.rn.satfinite.f16x2.f32 %0, %1, %2;" : "=r"(AH[ks * 4 + q]) : "f"(w1), "f"(w0));
            }
        }
        #pragma unroll
        for (int ks = 0; ks < 4; ks++) {
            u32* ahi = AH + ks * 4;
            u32 abH = whHb + bo + (hf * 64 + ks * 16) * 144 + laneoff;
            #pragma unroll
            for (int nb = 0; nb < 4; nb++) {
                u32 bh0, bh1, bh2, bh3;
                asm volatile("ldmatrix.sync.aligned.m8n8.x4.trans.shared.b16 {%0,%1,%2,%3}, [%4];"
                    : "=r"(bh0), "=r"(bh1), "=r"(bh2), "=r"(bh3) : "r"(abH + nb * 32));
                MMA(D[nb * 2],     ahi, bh0, bh1);
                MMA(D[nb * 2 + 1], ahi, bh2, bh3);
            }
        }
    };

    issueTile(0);
    CPC();
    u32 bC0 = loadBits(0, 0), bC1 = loadBits(0, 1);
    u32 bN0 = 0, bN1 = 0;

    for (int st = 0; st < NSUB; st++) {
        CPW0();             // tile st resident
        __syncthreads();    // all warps done with buffer (st+1)&1

        if (st < NSUB - 1) {
            issueTile(st + 1);
            CPC();
            bN0 = loadBits(st + 1, 0);
        }
        half64(st, 0, bC0);
        if (st < NSUB - 1) bN1 = loadBits(st + 1, 1);
        half64(st, 1, bC1);

        bC0 = bN0; bC1 = bN1;
    }

    // ---- epilogue: Z quad-reduce + partial stores ----
    z0 += __shfl_xor_sync(0xffffffffu, z0, 1);
    z0 += __shfl_xor_sync(0xffffffffu, z0, 2);
    z1 += __shfl_xor_sync(0xffffffffu, z1, 1);
    z1 += __shfl_xor_sync(0xffffffffu, z1, 2);
    if (tc == 0) {
        g_Zp[blk * RT + wid * 16 + g]     = z0;
        g_Zp[blk * RT + wid * 16 + 8 + g] = z1;
    }
    float* db = g_Dp + (size_t)blk * RT * FOUT + (size_t)(wid * 16 + g) * FOUT + tc * 2;
    #pragma unroll
    for (int nt = 0; nt < 8; nt++) {
        *(float2*)(db + nt * 8)             = make_float2(D[nt][0], D[nt][1]);
        *(float2*)(db + 8 * FOUT + nt * 8)  = make_float2(D[nt][2], D[nt][3]);
    }
}

// ---------------------------------------------------------------------------
// Kernel 3: combine 4 j-quarters: out = elu(SumD/SumZ)
// ---------------------------------------------------------------------------
__global__ __launch_bounds__(256) void k_comb(float* __restrict__ out) {
    int idx = blockIdx.x * 256 + threadIdx.x;   // x4 floats
    int i  = idx >> 4;
    int f4 = (idx & 15) * 4;
    int rt = i >> 7, r = i & 127;
    float4 d = make_float4(0.f, 0.f, 0.f, 0.f);
    float z = 0.f;
    #pragma unroll
    for (int p = 0; p < 4; p++) {
        int b = rt * 4 + p;
        const float4 dp = *(const float4*)(g_Dp + (size_t)b * (RT * FOUT) + r * FOUT + f4);
        d.x += dp.x; d.y += dp.y; d.z += dp.z; d.w += dp.w;
        z += g_Zp[b * RT + r];
    }
    float inv = 1.0f / z;
    float v[4] = {d.x * inv, d.y * inv, d.z * inv, d.w * inv};
    #pragma unroll
    for (int c = 0; c < 4; c++) v[c] = (v[c] > 0.f) ? v[c] : expm1f(v[c]);
    *(float4*)(out + (size_t)i * FOUT + f4) = make_float4(v[0], v[1], v[2], v[3]);
}

// ---------------------------------------------------------------------------
extern "C" void kernel_launch(void* const* d_in, const int* in_sizes, int n_in,
                              void* d_out, int out_size) {
    const float* h   = (const float*)d_in[0];
    const int*   adj = (const int*)  d_in[1];
    const float* W   = (const float*)d_in[2];
    const float* a   = (const float*)d_in[3];
    float* out = (float*)d_out;

    cudaFuncSetAttribute(k_prep, cudaFuncAttributeMaxDynamicSharedMemorySize, 99840);
    k_prep<<<NN / 32, 256, 99840>>>(h, W, a);
    k_main<<<NBLK, 256>>>(adj);
    k_comb<<<NN * FOUT / 4 / 256, 256>>>(out);
}